// round 1
// baseline (speedup 1.0000x reference)
#include <cuda_runtime.h>
#include <cstdint>

#define D 512
#define SRC 128
#define TGT_STEPS 128
#define VOCAB 50000

// ---------------- scratch (device globals; no allocation allowed) ----------------
__device__ __align__(16) float g_xpre[SRC * D];
__device__ __align__(16) float g_epre[TGT_STEPS * D];
__device__ __align__(16) float g_fencs[SRC * D];
__device__ __align__(16) float g_H[TGT_STEPS * D];
__device__ __align__(16) float g_CH[TGT_STEPS * 2 * D];
__device__ __align__(16) float g_M[TGT_STEPS * D];
__device__ float g_sumexp[TGT_STEPS];
__device__ float g_picked[TGT_STEPS];
__device__ unsigned g_cnt;
__device__ unsigned g_flag;

// ---------------- helpers ----------------
__device__ __forceinline__ unsigned long long pk2(float x, float y) {
    unsigned long long r;
    asm("mov.b64 %0, {%1, %2};" : "=l"(r) : "f"(x), "f"(y));
    return r;
}
__device__ __forceinline__ float2 upk2(unsigned long long v) {
    float2 r;
    asm("mov.b64 {%0, %1}, %2;" : "=f"(r.x), "=f"(r.y) : "l"(v));
    return r;
}
__device__ __forceinline__ void fma2(unsigned long long& d, unsigned long long a, unsigned long long b) {
    asm volatile("fma.rn.f32x2 %0, %1, %2, %0;" : "+l"(d) : "l"(a), "l"(b));
}

// ---------------- init: reset per-launch state ----------------
__global__ void init_kernel() {
    int i = threadIdx.x;
    if (i < TGT_STEPS) g_sumexp[i] = 0.f;
    if (i == 0) { g_cnt = 0u; g_flag = 0u; }
}

// ---------------- K1: pre-activations Xpre/Epre ----------------
// grid (16, 2), 256 threads. blockIdx.y: 0 = encoder, 1 = decoder.
__global__ void pre_kernel(const int* __restrict__ fnums, const int* __restrict__ enums,
                           const float* __restrict__ emb_f, const float* __restrict__ emb_d,
                           const float* __restrict__ Wih_e, const float* __restrict__ Wih_d,
                           const float* __restrict__ b_e, const float* __restrict__ b_d) {
    int which = blockIdx.y;
    const float* emb = which ? emb_d : emb_f;
    const int* idx = which ? enums : fnums;   // decoder uses enums[0..127] (inp)
    const float* W = which ? Wih_d : Wih_e;
    const float* b = which ? b_d : b_e;
    float* out = which ? g_epre : g_xpre;

    __shared__ __align__(16) float xs[8][D];
    int t0 = blockIdx.x * 8;
    for (int i = threadIdx.x; i < 8 * D; i += 256) {
        int tt = i >> 9, d = i & (D - 1);
        xs[tt][d] = emb[(size_t)idx[t0 + tt] * D + d];
    }
    __syncthreads();

    int w = threadIdx.x >> 5, l = threadIdx.x & 31;
    for (int dd = 0; dd < 64; dd++) {
        int d = w * 64 + dd;
        float4 wv[4];
#pragma unroll
        for (int j = 0; j < 4; j++) wv[j] = *(const float4*)&W[d * D + l * 4 + j * 128];
#pragma unroll
        for (int tt = 0; tt < 8; tt++) {
            float acc = 0.f;
#pragma unroll
            for (int j = 0; j < 4; j++) {
                float4 xv = *(const float4*)&xs[tt][l * 4 + j * 128];
                acc += wv[j].x * xv.x + wv[j].y * xv.y + wv[j].z * xv.z + wv[j].w * xv.w;
            }
#pragma unroll
            for (int o = 16; o; o >>= 1) acc += __shfl_xor_sync(0xffffffffu, acc, o);
            if (l == 0) out[(t0 + tt) * D + d] = acc + b[d];
        }
    }
}

// ---------------- K2: both recurrences, persistent grid with software barrier ----------------
__device__ __forceinline__ void gridbar(unsigned target) {
    __syncthreads();
    if (threadIdx.x == 0) {
        __threadfence();
        unsigned arrived = atomicAdd(&g_cnt, 1u) + 1u;
        if (arrived == target * 128u) {
            __threadfence();
            *(volatile unsigned*)&g_flag = target;
        } else {
            while (*(volatile unsigned*)&g_flag < target) {}
        }
        __threadfence();
    }
    __syncthreads();
}

// grid 128 CTAs x 128 threads. warp w of CTA b owns output row b*4+w.
__global__ void recur_kernel(const float* __restrict__ Whh_e, const float* __restrict__ Whh_d,
                             const float* __restrict__ h0_e, const float* __restrict__ h0_d) {
    int w = threadIdx.x >> 5, l = threadIdx.x & 31;
    int row = blockIdx.x * 4 + w;
    unsigned s = 0;
    for (int ph = 0; ph < 2; ph++) {
        const float* W = ph ? Whh_d : Whh_e;
        const float* h0 = ph ? h0_d : h0_e;
        const float* pre = ph ? g_epre : g_xpre;
        float* out = ph ? g_H : g_fencs;
        float4 wv[4];
#pragma unroll
        for (int j = 0; j < 4; j++) wv[j] = *(const float4*)&W[row * D + l * 4 + j * 128];
        for (int t = 0; t < 128; t++) {
            const float* hp = (t == 0) ? h0 : &out[(t - 1) * D];
            float acc = 0.f;
#pragma unroll
            for (int j = 0; j < 4; j++) {
                float4 hv = *(const float4*)&hp[l * 4 + j * 128];
                acc = fmaf(wv[j].x, hv.x, fmaf(wv[j].y, hv.y, fmaf(wv[j].z, hv.z, fmaf(wv[j].w, hv.w, acc))));
            }
#pragma unroll
            for (int o = 16; o; o >>= 1) acc += __shfl_xor_sync(0xffffffffu, acc, o);
            if (l == 0) out[t * D + row] = tanhf(acc + pre[t * D + row]);
            s++;
            gridbar(s);
        }
    }
}

// ---------------- K3: attention per decoder step (batched over t) ----------------
// grid 128 (one CTA per t), 128 threads
__global__ void attn_kernel() {
    int t = blockIdx.x;
    int tid = threadIdx.x, w = tid >> 5, l = tid & 31;
    __shared__ __align__(16) float hs[D];
    __shared__ float sc[SRC];
    __shared__ float red[8];
    for (int i = tid; i < D; i += 128) hs[i] = g_H[t * D + i];
    __syncthreads();
#pragma unroll 1
    for (int si = 0; si < 32; si++) {
        int s2 = w * 32 + si;
        float acc = 0.f;
#pragma unroll
        for (int j = 0; j < 4; j++) {
            float4 fv = *(const float4*)&g_fencs[s2 * D + l * 4 + j * 128];
            float4 hv = *(const float4*)&hs[l * 4 + j * 128];
            acc += fv.x * hv.x + fv.y * hv.y + fv.z * hv.z + fv.w * hv.w;
        }
#pragma unroll
        for (int o = 16; o; o >>= 1) acc += __shfl_xor_sync(0xffffffffu, acc, o);
        if (l == 0) sc[s2] = acc;
    }
    __syncthreads();
    float v = sc[tid];
    float mx = v;
#pragma unroll
    for (int o = 16; o; o >>= 1) mx = fmaxf(mx, __shfl_xor_sync(0xffffffffu, mx, o));
    if (l == 0) red[w] = mx;
    __syncthreads();
    mx = fmaxf(fmaxf(red[0], red[1]), fmaxf(red[2], red[3]));
    float e = __expf(v - mx);
    float sm = e;
#pragma unroll
    for (int o = 16; o; o >>= 1) sm += __shfl_xor_sync(0xffffffffu, sm, o);
    if (l == 0) red[4 + w] = sm;
    __syncthreads();
    sm = red[4] + red[5] + red[6] + red[7];
    sc[tid] = e / sm;
    __syncthreads();
    for (int d = tid; d < D; d += 128) {
        float c = 0.f;
#pragma unroll 8
        for (int s2 = 0; s2 < SRC; s2++) c = fmaf(sc[s2], g_fencs[s2 * D + d], c);
        g_CH[t * 2 * D + d] = c;
        g_CH[t * 2 * D + D + d] = hs[d];
    }
}

// ---------------- K4: M = tanh(CH @ Wm^T + bm) ----------------
// grid (8, 16), 256 threads: 64 d x 8 t per CTA
__global__ void m_kernel(const float* __restrict__ Wm, const float* __restrict__ bm) {
    int w = threadIdx.x >> 5, l = threadIdx.x & 31;
    int t0 = blockIdx.y * 8;
#pragma unroll 1
    for (int dd = 0; dd < 8; dd++) {
        int d = blockIdx.x * 64 + w * 8 + dd;
        float4 wv[8];
#pragma unroll
        for (int j = 0; j < 8; j++) wv[j] = *(const float4*)&Wm[d * 2 * D + l * 4 + j * 128];
#pragma unroll
        for (int tt = 0; tt < 8; tt++) {
            int t = t0 + tt;
            float acc = 0.f;
#pragma unroll
            for (int j = 0; j < 8; j++) {
                float4 cv = *(const float4*)&g_CH[t * 2 * D + l * 4 + j * 128];
                acc += wv[j].x * cv.x + wv[j].y * cv.y + wv[j].z * cv.z + wv[j].w * cv.w;
            }
#pragma unroll
            for (int o = 16; o; o >>= 1) acc += __shfl_xor_sync(0xffffffffu, acc, o);
            if (l == 0) g_M[t * D + d] = tanhf(acc + bm[d]);
        }
    }
}

// ---------------- K5: logits GEMM (128 x 50000 x 512) + fused exp-sum + target gather ----------------
// grid 391 (vocab tiles of 128), 256 threads, 8x8 micro-tiles, packed f32x2 FMA.
__global__ void __launch_bounds__(256) logits_kernel(const float* __restrict__ Wo,
                                                     const float* __restrict__ bo,
                                                     const int* __restrict__ enums) {
    __shared__ __align__(16) float As[16][132];
    __shared__ __align__(16) float Bs[16][132];
    int tid = threadIdx.x;
    int tx = tid & 15, ty = tid >> 4;
    int vb = blockIdx.x * 128;
    int lr = tid >> 1;
    int lc = (tid & 1) * 8;

    unsigned long long acc[8][4];
#pragma unroll
    for (int i = 0; i < 8; i++)
#pragma unroll
        for (int c = 0; c < 4; c++) acc[i][c] = 0ull;

    int v_l = vb + lr;
    float4 a0 = *(const float4*)&g_M[lr * D + lc];
    float4 a1 = *(const float4*)&g_M[lr * D + lc + 4];
    float4 b0 = make_float4(0, 0, 0, 0), b1 = make_float4(0, 0, 0, 0);
    if (v_l < VOCAB) {
        b0 = *(const float4*)&Wo[(size_t)v_l * D + lc];
        b1 = *(const float4*)&Wo[(size_t)v_l * D + lc + 4];
    }

    for (int kt = 0; kt < D; kt += 16) {
        __syncthreads();
        As[lc + 0][lr] = a0.x; As[lc + 1][lr] = a0.y; As[lc + 2][lr] = a0.z; As[lc + 3][lr] = a0.w;
        As[lc + 4][lr] = a1.x; As[lc + 5][lr] = a1.y; As[lc + 6][lr] = a1.z; As[lc + 7][lr] = a1.w;
        Bs[lc + 0][lr] = b0.x; Bs[lc + 1][lr] = b0.y; Bs[lc + 2][lr] = b0.z; Bs[lc + 3][lr] = b0.w;
        Bs[lc + 4][lr] = b1.x; Bs[lc + 5][lr] = b1.y; Bs[lc + 6][lr] = b1.z; Bs[lc + 7][lr] = b1.w;
        __syncthreads();
        if (kt + 16 < D) {
            a0 = *(const float4*)&g_M[lr * D + kt + 16 + lc];
            a1 = *(const float4*)&g_M[lr * D + kt + 16 + lc + 4];
            if (v_l < VOCAB) {
                b0 = *(const float4*)&Wo[(size_t)v_l * D + kt + 16 + lc];
                b1 = *(const float4*)&Wo[(size_t)v_l * D + kt + 16 + lc + 4];
            }
        }
#pragma unroll
        for (int k = 0; k < 16; k++) {
            float4 av0 = *(const float4*)&As[k][ty * 8];
            float4 av1 = *(const float4*)&As[k][ty * 8 + 4];
            float4 bv0 = *(const float4*)&Bs[k][tx * 8];
            float4 bv1 = *(const float4*)&Bs[k][tx * 8 + 4];
            unsigned long long bb0 = pk2(bv0.x, bv0.y), bb1 = pk2(bv0.z, bv0.w);
            unsigned long long bb2 = pk2(bv1.x, bv1.y), bb3 = pk2(bv1.z, bv1.w);
            float a[8] = {av0.x, av0.y, av0.z, av0.w, av1.x, av1.y, av1.z, av1.w};
#pragma unroll
            for (int i = 0; i < 8; i++) {
                unsigned long long aa = pk2(a[i], a[i]);
                fma2(acc[i][0], aa, bb0);
                fma2(acc[i][1], aa, bb1);
                fma2(acc[i][2], aa, bb2);
                fma2(acc[i][3], aa, bb3);
            }
        }
    }

    // epilogue: logits are tiny (|logit| < ~0.3), so no max-subtraction needed
    float bov[8];
    int vs[8];
#pragma unroll
    for (int c = 0; c < 8; c++) {
        int v = vb + tx * 8 + c;
        vs[c] = v;
        bov[c] = (v < VOCAB) ? bo[v] : 0.f;
    }
#pragma unroll
    for (int i = 0; i < 8; i++) {
        int t = ty * 8 + i;
        int tgt = enums[t + 1];
        float s = 0.f;
#pragma unroll
        for (int c = 0; c < 4; c++) {
            float2 lg = upk2(acc[i][c]);
            float l0 = lg.x + bov[2 * c], l1 = lg.y + bov[2 * c + 1];
            if (vs[2 * c] < VOCAB) {
                s += __expf(l0);
                if (vs[2 * c] == tgt) g_picked[t] = l0;
            }
            if (vs[2 * c + 1] < VOCAB) {
                s += __expf(l1);
                if (vs[2 * c + 1] == tgt) g_picked[t] = l1;
            }
        }
#pragma unroll
        for (int o = 8; o; o >>= 1) s += __shfl_xor_sync(0xffffffffu, s, o);
        if (tx == 0) atomicAdd(&g_sumexp[t], s);
    }
}

// ---------------- K6: final reduction ----------------
__global__ void finalize_kernel(float* __restrict__ out) {
    int tid = threadIdx.x;  // 128
    float v = g_picked[tid] - logf(g_sumexp[tid]);
    __shared__ float red[4];
    int w = tid >> 5, l = tid & 31;
#pragma unroll
    for (int o = 16; o; o >>= 1) v += __shfl_xor_sync(0xffffffffu, v, o);
    if (l == 0) red[w] = v;
    __syncthreads();
    if (tid == 0) out[0] = red[0] + red[1] + red[2] + red[3];
}

// ---------------- launch ----------------
extern "C" void kernel_launch(void* const* d_in, const int* in_sizes, int n_in,
                              void* d_out, int out_size) {
    const int* fnums = (const int*)d_in[0];
    const int* enums = (const int*)d_in[1];
    const float* emb_f = (const float*)d_in[2];
    const float* Wih_e = (const float*)d_in[3];
    const float* Whh_e = (const float*)d_in[4];
    const float* b_e = (const float*)d_in[5];
    const float* h0_e = (const float*)d_in[6];
    const float* emb_d = (const float*)d_in[7];
    const float* Wih_d = (const float*)d_in[8];
    const float* Whh_d = (const float*)d_in[9];
    const float* b_d = (const float*)d_in[10];
    const float* h0_d = (const float*)d_in[11];
    const float* Wm = (const float*)d_in[12];
    const float* bm = (const float*)d_in[13];
    const float* Wo = (const float*)d_in[14];
    const float* bo = (const float*)d_in[15];
    float* out = (float*)d_out;

    init_kernel<<<1, 128>>>();
    pre_kernel<<<dim3(16, 2), 256>>>(fnums, enums, emb_f, emb_d, Wih_e, Wih_d, b_e, b_d);
    recur_kernel<<<128, 128>>>(Whh_e, Whh_d, h0_e, h0_d);
    attn_kernel<<<128, 128>>>();
    m_kernel<<<dim3(8, 16), 256>>>(Wm, bm);
    logits_kernel<<<(VOCAB + 127) / 128, 256>>>(Wo, bo, enums);
    finalize_kernel<<<1, 128>>>(out);
}

// round 2
// speedup vs baseline: 2.0420x; 2.0420x over previous
#include <cuda_runtime.h>
#include <cstdint>

#define D 512
#define SRC 128
#define TGT_STEPS 128
#define VOCAB 50000

// ---------------- scratch (device globals; no allocation allowed) ----------------
__device__ __align__(16) float g_xpre[SRC * D];
__device__ __align__(16) float g_epre[TGT_STEPS * D];
__device__ __align__(16) float g_fencs[SRC * D];
__device__ __align__(16) float g_H[TGT_STEPS * D];
__device__ __align__(16) float g_alpha[TGT_STEPS * SRC];
__device__ __align__(16) float g_CH[TGT_STEPS * 2 * D];
__device__ __align__(16) float g_M[TGT_STEPS * D];
__device__ float g_sumexp[TGT_STEPS];
__device__ float g_picked[TGT_STEPS];

// ---------------- helpers ----------------
__device__ __forceinline__ unsigned long long pk2(float x, float y) {
    unsigned long long r;
    asm("mov.b64 %0, {%1, %2};" : "=l"(r) : "f"(x), "f"(y));
    return r;
}
__device__ __forceinline__ float2 upk2(unsigned long long v) {
    float2 r;
    asm("mov.b64 {%0, %1}, %2;" : "=f"(r.x), "=f"(r.y) : "l"(v));
    return r;
}
__device__ __forceinline__ void fma2(unsigned long long& d, unsigned long long a, unsigned long long b) {
    asm volatile("fma.rn.f32x2 %0, %1, %2, %0;" : "+l"(d) : "l"(a), "l"(b));
}
__device__ __forceinline__ void st_cluster_f32(uint32_t saddr, uint32_t rank, float v) {
    uint32_t r;
    asm volatile("mapa.shared::cluster.u32 %0, %1, %2;" : "=r"(r) : "r"(saddr), "r"(rank));
    asm volatile("st.shared::cluster.f32 [%0], %1;" :: "r"(r), "f"(v) : "memory");
}

// ---------------- init ----------------
__global__ void init_kernel() {
    int i = threadIdx.x;
    if (i < TGT_STEPS) g_sumexp[i] = 0.f;
}

// ---------------- K1: pre-activations Xpre/Epre ----------------
__global__ void pre_kernel(const int* __restrict__ fnums, const int* __restrict__ enums,
                           const float* __restrict__ emb_f, const float* __restrict__ emb_d,
                           const float* __restrict__ Wih_e, const float* __restrict__ Wih_d,
                           const float* __restrict__ b_e, const float* __restrict__ b_d) {
    int which = blockIdx.y;
    const float* emb = which ? emb_d : emb_f;
    const int* idx = which ? enums : fnums;
    const float* W = which ? Wih_d : Wih_e;
    const float* b = which ? b_d : b_e;
    float* out = which ? g_epre : g_xpre;

    __shared__ __align__(16) float xs[8][D];
    int t0 = blockIdx.x * 8;
    for (int i = threadIdx.x; i < 8 * D; i += 256) {
        int tt = i >> 9, d = i & (D - 1);
        xs[tt][d] = emb[(size_t)idx[t0 + tt] * D + d];
    }
    __syncthreads();

    int w = threadIdx.x >> 5, l = threadIdx.x & 31;
    for (int dd = 0; dd < 64; dd++) {
        int d = w * 64 + dd;
        float4 wv[4];
#pragma unroll
        for (int j = 0; j < 4; j++) wv[j] = *(const float4*)&W[d * D + l * 4 + j * 128];
#pragma unroll
        for (int tt = 0; tt < 8; tt++) {
            float acc = 0.f;
#pragma unroll
            for (int j = 0; j < 4; j++) {
                float4 xv = *(const float4*)&xs[tt][l * 4 + j * 128];
                acc += wv[j].x * xv.x + wv[j].y * xv.y + wv[j].z * xv.z + wv[j].w * xv.w;
            }
#pragma unroll
            for (int o = 16; o; o >>= 1) acc += __shfl_xor_sync(0xffffffffu, acc, o);
            if (l == 0) out[(t0 + tt) * D + d] = acc + b[d];
        }
    }
}

// ---------------- K2: both recurrences, one 8-CTA cluster each ----------------
// grid (8, 2) with cluster dims (8,1,1): gridDim.y=0 encoder cluster, =1 decoder cluster.
// 512 threads/CTA. Thread (rl, sub): rl = tid>>3 local row (CTA owns rows rank*64+rl),
// sub = tid&7 handles cols {j*32 + sub*4 + e}. Weights live in 64 registers/thread.
__global__ void __cluster_dims__(8, 1, 1) __launch_bounds__(512, 1)
recur_kernel(const float* __restrict__ Whh_e, const float* __restrict__ Whh_d,
             const float* __restrict__ h0_e, const float* __restrict__ h0_d) {
    const int ph = blockIdx.y;
    const float* W = ph ? Whh_d : Whh_e;
    const float* h0 = ph ? h0_d : h0_e;
    const float* pre = ph ? g_epre : g_xpre;
    float* outg = ph ? g_H : g_fencs;

    __shared__ __align__(16) float hbuf[2][D];
    __shared__ float pre_s[128 * 64];  // this CTA's 64 rows, all 128 steps (32KB)

    const int tid = threadIdx.x;
    const int rl = tid >> 3;       // 0..63
    const int sub = tid & 7;       // 0..7
    const uint32_t rank = blockIdx.x;  // cluster ctarank (cluster spans x)
    const int row = rank * 64 + rl;

    // weights: 64 floats = 16 float4, col block j covers cols j*32+sub*4 .. +3
    float4 wv[16];
#pragma unroll
    for (int j = 0; j < 16; j++)
        wv[j] = *(const float4*)&W[row * D + j * 32 + sub * 4];

    // preload pre for own rows, and h0
    for (int i = tid; i < 128 * 64; i += 512) {
        int t = i >> 6, r = i & 63;
        pre_s[i] = pre[t * D + rank * 64 + r];
    }
    if (tid < D) hbuf[0][tid] = h0[tid];
    __syncthreads();

    int p = 0;
    for (int t = 0; t < 128; t++) {
        const float* hp = hbuf[p];
        float a0 = 0.f, a1 = 0.f, a2 = 0.f, a3 = 0.f;
#pragma unroll
        for (int j = 0; j < 16; j++) {
            float4 hv = *(const float4*)&hp[j * 32 + sub * 4];
            a0 = fmaf(wv[j].x, hv.x, a0);
            a1 = fmaf(wv[j].y, hv.y, a1);
            a2 = fmaf(wv[j].z, hv.z, a2);
            a3 = fmaf(wv[j].w, hv.w, a3);
        }
        float acc = (a0 + a1) + (a2 + a3);
#pragma unroll
        for (int o = 4; o; o >>= 1) acc += __shfl_xor_sync(0xffffffffu, acc, o);
        if (sub == 0) {
            float h = tanhf(acc + pre_s[t * 64 + rl]);
            uint32_t dst = (uint32_t)__cvta_generic_to_shared(&hbuf[p ^ 1][row]);
#pragma unroll
            for (uint32_t c = 0; c < 8; c++) st_cluster_f32(dst, c, h);
            outg[t * D + row] = h;
        }
        asm volatile("barrier.cluster.arrive.aligned;" ::: "memory");
        asm volatile("barrier.cluster.wait.aligned;" ::: "memory");
        p ^= 1;
    }
}

// ---------------- K3a: scores + softmax -> g_alpha ----------------
// grid 128 (t), 256 threads; warp w computes 16 scores
__global__ void attn_scores_kernel() {
    int t = blockIdx.x;
    int tid = threadIdx.x, w = tid >> 5, l = tid & 31;
    __shared__ __align__(16) float hs[D];
    __shared__ float sc[SRC];
    __shared__ float red[16];
    for (int i = tid; i < D; i += 256) hs[i] = g_H[t * D + i];
    __syncthreads();
#pragma unroll 1
    for (int si = 0; si < 16; si++) {
        int s2 = w * 16 + si;
        float acc = 0.f;
#pragma unroll
        for (int j = 0; j < 4; j++) {
            float4 fv = *(const float4*)&g_fencs[s2 * D + l * 4 + j * 128];
            float4 hv = *(const float4*)&hs[l * 4 + j * 128];
            acc += fv.x * hv.x + fv.y * hv.y + fv.z * hv.z + fv.w * hv.w;
        }
#pragma unroll
        for (int o = 16; o; o >>= 1) acc += __shfl_xor_sync(0xffffffffu, acc, o);
        if (l == 0) sc[s2] = acc;
    }
    __syncthreads();
    // softmax over 128 scores, done by first 128 threads
    float v = (tid < SRC) ? sc[tid] : -1e30f;
    float mx = v;
#pragma unroll
    for (int o = 16; o; o >>= 1) mx = fmaxf(mx, __shfl_xor_sync(0xffffffffu, mx, o));
    if (l == 0) red[w] = mx;
    __syncthreads();
    mx = fmaxf(fmaxf(red[0], red[1]), fmaxf(red[2], red[3]));
    float e = (tid < SRC) ? __expf(v - mx) : 0.f;
    float sm = e;
#pragma unroll
    for (int o = 16; o; o >>= 1) sm += __shfl_xor_sync(0xffffffffu, sm, o);
    if (l == 0) red[8 + w] = sm;
    __syncthreads();
    sm = red[8] + red[9] + red[10] + red[11];
    if (tid < SRC) g_alpha[t * SRC + tid] = e / sm;
}

// ---------------- K3b: context + assemble CH ----------------
// grid (128 t, 4 d-chunks), 128 threads: thread owns one d
__global__ void attn_ctx_kernel() {
    int t = blockIdx.x;
    int d = blockIdx.y * 128 + threadIdx.x;
    __shared__ float al[SRC];
    al[threadIdx.x] = g_alpha[t * SRC + threadIdx.x];
    __syncthreads();
    float c = 0.f;
#pragma unroll 16
    for (int s = 0; s < SRC; s++) c = fmaf(al[s], g_fencs[s * D + d], c);
    g_CH[t * 2 * D + d] = c;
    g_CH[t * 2 * D + D + d] = g_H[t * D + d];
}

// ---------------- K4: M = tanh(CH @ Wm^T + bm) ----------------
__global__ void m_kernel(const float* __restrict__ Wm, const float* __restrict__ bm) {
    int w = threadIdx.x >> 5, l = threadIdx.x & 31;
    int t0 = blockIdx.y * 8;
#pragma unroll 1
    for (int dd = 0; dd < 8; dd++) {
        int d = blockIdx.x * 64 + w * 8 + dd;
        float4 wv[8];
#pragma unroll
        for (int j = 0; j < 8; j++) wv[j] = *(const float4*)&Wm[d * 2 * D + l * 4 + j * 128];
#pragma unroll
        for (int tt = 0; tt < 8; tt++) {
            int t = t0 + tt;
            float acc = 0.f;
#pragma unroll
            for (int j = 0; j < 8; j++) {
                float4 cv = *(const float4*)&g_CH[t * 2 * D + l * 4 + j * 128];
                acc += wv[j].x * cv.x + wv[j].y * cv.y + wv[j].z * cv.z + wv[j].w * cv.w;
            }
#pragma unroll
            for (int o = 16; o; o >>= 1) acc += __shfl_xor_sync(0xffffffffu, acc, o);
            if (l == 0) g_M[t * D + d] = tanhf(acc + bm[d]);
        }
    }
}

// ---------------- K5: logits GEMM + fused exp-sum + target gather ----------------
__global__ void __launch_bounds__(256) logits_kernel(const float* __restrict__ Wo,
                                                     const float* __restrict__ bo,
                                                     const int* __restrict__ enums) {
    __shared__ __align__(16) float As[16][132];
    __shared__ __align__(16) float Bs[16][132];
    int tid = threadIdx.x;
    int tx = tid & 15, ty = tid >> 4;
    int vb = blockIdx.x * 128;
    int lr = tid >> 1;
    int lc = (tid & 1) * 8;

    unsigned long long acc[8][4];
#pragma unroll
    for (int i = 0; i < 8; i++)
#pragma unroll
        for (int c = 0; c < 4; c++) acc[i][c] = 0ull;

    int v_l = vb + lr;
    float4 a0 = *(const float4*)&g_M[lr * D + lc];
    float4 a1 = *(const float4*)&g_M[lr * D + lc + 4];
    float4 b0 = make_float4(0, 0, 0, 0), b1 = make_float4(0, 0, 0, 0);
    if (v_l < VOCAB) {
        b0 = *(const float4*)&Wo[(size_t)v_l * D + lc];
        b1 = *(const float4*)&Wo[(size_t)v_l * D + lc + 4];
    }

    for (int kt = 0; kt < D; kt += 16) {
        __syncthreads();
        As[lc + 0][lr] = a0.x; As[lc + 1][lr] = a0.y; As[lc + 2][lr] = a0.z; As[lc + 3][lr] = a0.w;
        As[lc + 4][lr] = a1.x; As[lc + 5][lr] = a1.y; As[lc + 6][lr] = a1.z; As[lc + 7][lr] = a1.w;
        Bs[lc + 0][lr] = b0.x; Bs[lc + 1][lr] = b0.y; Bs[lc + 2][lr] = b0.z; Bs[lc + 3][lr] = b0.w;
        Bs[lc + 4][lr] = b1.x; Bs[lc + 5][lr] = b1.y; Bs[lc + 6][lr] = b1.z; Bs[lc + 7][lr] = b1.w;
        __syncthreads();
        if (kt + 16 < D) {
            a0 = *(const float4*)&g_M[lr * D + kt + 16 + lc];
            a1 = *(const float4*)&g_M[lr * D + kt + 16 + lc + 4];
            if (v_l < VOCAB) {
                b0 = *(const float4*)&Wo[(size_t)v_l * D + kt + 16 + lc];
                b1 = *(const float4*)&Wo[(size_t)v_l * D + kt + 16 + lc + 4];
            }
        }
#pragma unroll
        for (int k = 0; k < 16; k++) {
            float4 av0 = *(const float4*)&As[k][ty * 8];
            float4 av1 = *(const float4*)&As[k][ty * 8 + 4];
            float4 bv0 = *(const float4*)&Bs[k][tx * 8];
            float4 bv1 = *(const float4*)&Bs[k][tx * 8 + 4];
            unsigned long long bb0 = pk2(bv0.x, bv0.y), bb1 = pk2(bv0.z, bv0.w);
            unsigned long long bb2 = pk2(bv1.x, bv1.y), bb3 = pk2(bv1.z, bv1.w);
            float a[8] = {av0.x, av0.y, av0.z, av0.w, av1.x, av1.y, av1.z, av1.w};
#pragma unroll
            for (int i = 0; i < 8; i++) {
                unsigned long long aa = pk2(a[i], a[i]);
                fma2(acc[i][0], aa, bb0);
                fma2(acc[i][1], aa, bb1);
                fma2(acc[i][2], aa, bb2);
                fma2(acc[i][3], aa, bb3);
            }
        }
    }

    float bov[8];
    int vs[8];
#pragma unroll
    for (int c = 0; c < 8; c++) {
        int v = vb + tx * 8 + c;
        vs[c] = v;
        bov[c] = (v < VOCAB) ? bo[v] : 0.f;
    }
#pragma unroll
    for (int i = 0; i < 8; i++) {
        int t = ty * 8 + i;
        int tgt = enums[t + 1];
        float s = 0.f;
#pragma unroll
        for (int c = 0; c < 4; c++) {
            float2 lg = upk2(acc[i][c]);
            float l0 = lg.x + bov[2 * c], l1 = lg.y + bov[2 * c + 1];
            if (vs[2 * c] < VOCAB) {
                s += __expf(l0);
                if (vs[2 * c] == tgt) g_picked[t] = l0;
            }
            if (vs[2 * c + 1] < VOCAB) {
                s += __expf(l1);
                if (vs[2 * c + 1] == tgt) g_picked[t] = l1;
            }
        }
#pragma unroll
        for (int o = 8; o; o >>= 1) s += __shfl_xor_sync(0xffffffffu, s, o);
        if (tx == 0) atomicAdd(&g_sumexp[t], s);
    }
}

// ---------------- K6: final reduction ----------------
__global__ void finalize_kernel(float* __restrict__ out) {
    int tid = threadIdx.x;
    float v = g_picked[tid] - logf(g_sumexp[tid]);
    __shared__ float red[4];
    int w = tid >> 5, l = tid & 31;
#pragma unroll
    for (int o = 16; o; o >>= 1) v += __shfl_xor_sync(0xffffffffu, v, o);
    if (l == 0) red[w] = v;
    __syncthreads();
    if (tid == 0) out[0] = red[0] + red[1] + red[2] + red[3];
}

// ---------------- launch ----------------
extern "C" void kernel_launch(void* const* d_in, const int* in_sizes, int n_in,
                              void* d_out, int out_size) {
    const int* fnums = (const int*)d_in[0];
    const int* enums = (const int*)d_in[1];
    const float* emb_f = (const float*)d_in[2];
    const float* Wih_e = (const float*)d_in[3];
    const float* Whh_e = (const float*)d_in[4];
    const float* b_e = (const float*)d_in[5];
    const float* h0_e = (const float*)d_in[6];
    const float* emb_d = (const float*)d_in[7];
    const float* Wih_d = (const float*)d_in[8];
    const float* Whh_d = (const float*)d_in[9];
    const float* b_d = (const float*)d_in[10];
    const float* h0_d = (const float*)d_in[11];
    const float* Wm = (const float*)d_in[12];
    const float* bm = (const float*)d_in[13];
    const float* Wo = (const float*)d_in[14];
    const float* bo = (const float*)d_in[15];
    float* out = (float*)d_out;

    init_kernel<<<1, 128>>>();
    pre_kernel<<<dim3(16, 2), 256>>>(fnums, enums, emb_f, emb_d, Wih_e, Wih_d, b_e, b_d);
    recur_kernel<<<dim3(8, 2), 512>>>(Whh_e, Whh_d, h0_e, h0_d);
    attn_scores_kernel<<<128, 256>>>();
    attn_ctx_kernel<<<dim3(128, 4), 128>>>();
    m_kernel<<<dim3(8, 16), 256>>>(Wm, bm);
    logits_kernel<<<(VOCAB + 127) / 128, 256>>>(Wo, bo, enums);
    finalize_kernel<<<1, 128>>>(out);
}

// round 4
// speedup vs baseline: 2.6351x; 1.2904x over previous
#include <cuda_runtime.h>
#include <cuda_bf16.h>
#include <cstdint>

#define D 512
#define SRC 128
#define TGT_STEPS 128
#define VOCAB 50000

// ---------------- scratch (device globals; no allocation allowed) ----------------
__device__ __align__(16) float g_xpre[SRC * D];
__device__ __align__(16) float g_epre[TGT_STEPS * D];
__device__ __align__(16) float g_fencs[SRC * D];
__device__ __align__(16) float g_H[TGT_STEPS * D];
__device__ __align__(16) float g_alpha[TGT_STEPS * SRC];
__device__ __align__(16) float g_CH[TGT_STEPS * 2 * D];
__device__ __align__(16) __nv_bfloat16 g_Mbf[TGT_STEPS * D];
__device__ float g_sumexp[TGT_STEPS];
__device__ float g_picked[TGT_STEPS];

// ---------------- helpers ----------------
__device__ __forceinline__ void st_cluster_f32(uint32_t saddr, uint32_t rank, float v) {
    uint32_t r;
    asm volatile("mapa.shared::cluster.u32 %0, %1, %2;" : "=r"(r) : "r"(saddr), "r"(rank));
    asm volatile("st.shared::cluster.f32 [%0], %1;" :: "r"(r), "f"(v) : "memory");
}
__device__ __forceinline__ uint32_t smem_u32(const void* p) {
    uint32_t a;
    asm("{ .reg .u64 t; cvta.to.shared.u64 t, %1; cvt.u32.u64 %0, t; }" : "=r"(a) : "l"(p));
    return a;
}
__device__ __forceinline__ void ldsm4(uint32_t& r0, uint32_t& r1, uint32_t& r2, uint32_t& r3,
                                      uint32_t addr) {
    asm volatile("ldmatrix.sync.aligned.m8n8.x4.shared.b16 {%0,%1,%2,%3}, [%4];"
                 : "=r"(r0), "=r"(r1), "=r"(r2), "=r"(r3) : "r"(addr));
}
__device__ __forceinline__ void mma_bf16(float* c, uint32_t a0, uint32_t a1, uint32_t a2,
                                         uint32_t a3, uint32_t b0, uint32_t b1) {
    asm volatile(
        "mma.sync.aligned.m16n8k16.row.col.f32.bf16.bf16.f32 "
        "{%0,%1,%2,%3}, {%4,%5,%6,%7}, {%8,%9}, {%0,%1,%2,%3};"
        : "+f"(c[0]), "+f"(c[1]), "+f"(c[2]), "+f"(c[3])
        : "r"(a0), "r"(a1), "r"(a2), "r"(a3), "r"(b0), "r"(b1));
}
__device__ __forceinline__ uint32_t sw128(uint32_t off) { return off ^ ((off >> 3) & 0x70); }

// ---------------- init ----------------
__global__ void init_kernel() {
    int i = threadIdx.x;
    if (i < TGT_STEPS) g_sumexp[i] = 0.f;
}

// ---------------- K1: pre-activations Xpre/Epre ----------------
__global__ void pre_kernel(const int* __restrict__ fnums, const int* __restrict__ enums,
                           const float* __restrict__ emb_f, const float* __restrict__ emb_d,
                           const float* __restrict__ Wih_e, const float* __restrict__ Wih_d,
                           const float* __restrict__ b_e, const float* __restrict__ b_d) {
    int which = blockIdx.y;
    const float* emb = which ? emb_d : emb_f;
    const int* idx = which ? enums : fnums;
    const float* W = which ? Wih_d : Wih_e;
    const float* b = which ? b_d : b_e;
    float* out = which ? g_epre : g_xpre;

    __shared__ __align__(16) float xs[8][D];
    int t0 = blockIdx.x * 8;
    for (int i = threadIdx.x; i < 8 * D; i += 256) {
        int tt = i >> 9, d = i & (D - 1);
        xs[tt][d] = emb[(size_t)idx[t0 + tt] * D + d];
    }
    __syncthreads();

    int w = threadIdx.x >> 5, l = threadIdx.x & 31;
    for (int dd = 0; dd < 64; dd++) {
        int d = w * 64 + dd;
        float4 wv[4];
#pragma unroll
        for (int j = 0; j < 4; j++) wv[j] = *(const float4*)&W[d * D + l * 4 + j * 128];
#pragma unroll
        for (int tt = 0; tt < 8; tt++) {
            float acc = 0.f;
#pragma unroll
            for (int j = 0; j < 4; j++) {
                float4 xv = *(const float4*)&xs[tt][l * 4 + j * 128];
                acc += wv[j].x * xv.x + wv[j].y * xv.y + wv[j].z * xv.z + wv[j].w * xv.w;
            }
#pragma unroll
            for (int o = 16; o; o >>= 1) acc += __shfl_xor_sync(0xffffffffu, acc, o);
            if (l == 0) out[(t0 + tt) * D + d] = acc + b[d];
        }
    }
}

// ---------------- K2: both recurrences, one 8-CTA cluster each ----------------
__global__ void __cluster_dims__(8, 1, 1) __launch_bounds__(512, 1)
recur_kernel(const float* __restrict__ Whh_e, const float* __restrict__ Whh_d,
             const float* __restrict__ h0_e, const float* __restrict__ h0_d) {
    const int ph = blockIdx.y;
    const float* W = ph ? Whh_d : Whh_e;
    const float* h0 = ph ? h0_d : h0_e;
    const float* pre = ph ? g_epre : g_xpre;
    float* outg = ph ? g_H : g_fencs;

    __shared__ __align__(16) float hbuf[2][D];
    __shared__ float pre_s[128 * 64];

    const int tid = threadIdx.x;
    const int rl = tid >> 3;
    const int sub = tid & 7;
    const uint32_t rank = blockIdx.x;
    const int row = rank * 64 + rl;

    float4 wv[16];
#pragma unroll
    for (int j = 0; j < 16; j++)
        wv[j] = *(const float4*)&W[row * D + j * 32 + sub * 4];

    for (int i = tid; i < 128 * 64; i += 512) {
        int t = i >> 6, r = i & 63;
        pre_s[i] = pre[t * D + rank * 64 + r];
    }
    if (tid < D) hbuf[0][tid] = h0[tid];
    __syncthreads();

    int p = 0;
    for (int t = 0; t < 128; t++) {
        const float* hp = hbuf[p];
        float a0 = 0.f, a1 = 0.f, a2 = 0.f, a3 = 0.f;
#pragma unroll
        for (int j = 0; j < 16; j++) {
            float4 hv = *(const float4*)&hp[j * 32 + sub * 4];
            a0 = fmaf(wv[j].x, hv.x, a0);
            a1 = fmaf(wv[j].y, hv.y, a1);
            a2 = fmaf(wv[j].z, hv.z, a2);
            a3 = fmaf(wv[j].w, hv.w, a3);
        }
        float acc = (a0 + a1) + (a2 + a3);
#pragma unroll
        for (int o = 4; o; o >>= 1) acc += __shfl_xor_sync(0xffffffffu, acc, o);
        if (sub == 0) {
            float h = tanhf(acc + pre_s[t * 64 + rl]);
            uint32_t dst = (uint32_t)__cvta_generic_to_shared(&hbuf[p ^ 1][row]);
#pragma unroll
            for (uint32_t c = 0; c < 8; c++) st_cluster_f32(dst, c, h);
            outg[t * D + row] = h;
        }
        asm volatile("barrier.cluster.arrive.aligned;" ::: "memory");
        asm volatile("barrier.cluster.wait.aligned;" ::: "memory");
        p ^= 1;
    }
}

// ---------------- K3a: scores + softmax -> g_alpha ----------------
__global__ void attn_scores_kernel() {
    int t = blockIdx.x;
    int tid = threadIdx.x, w = tid >> 5, l = tid & 31;
    __shared__ __align__(16) float hs[D];
    __shared__ float sc[SRC];
    __shared__ float red[16];
    for (int i = tid; i < D; i += 256) hs[i] = g_H[t * D + i];
    __syncthreads();
#pragma unroll 1
    for (int si = 0; si < 16; si++) {
        int s2 = w * 16 + si;
        float acc = 0.f;
#pragma unroll
        for (int j = 0; j < 4; j++) {
            float4 fv = *(const float4*)&g_fencs[s2 * D + l * 4 + j * 128];
            float4 hv = *(const float4*)&hs[l * 4 + j * 128];
            acc += fv.x * hv.x + fv.y * hv.y + fv.z * hv.z + fv.w * hv.w;
        }
#pragma unroll
        for (int o = 16; o; o >>= 1) acc += __shfl_xor_sync(0xffffffffu, acc, o);
        if (l == 0) sc[s2] = acc;
    }
    __syncthreads();
    float v = (tid < SRC) ? sc[tid] : -1e30f;
    float mx = v;
#pragma unroll
    for (int o = 16; o; o >>= 1) mx = fmaxf(mx, __shfl_xor_sync(0xffffffffu, mx, o));
    if (l == 0) red[w] = mx;
    __syncthreads();
    mx = fmaxf(fmaxf(red[0], red[1]), fmaxf(red[2], red[3]));
    float e = (tid < SRC) ? __expf(v - mx) : 0.f;
    float sm = e;
#pragma unroll
    for (int o = 16; o; o >>= 1) sm += __shfl_xor_sync(0xffffffffu, sm, o);
    if (l == 0) red[8 + w] = sm;
    __syncthreads();
    sm = red[8] + red[9] + red[10] + red[11];
    if (tid < SRC) g_alpha[t * SRC + tid] = e / sm;
}

// ---------------- K3b: context + assemble CH ----------------
__global__ void attn_ctx_kernel() {
    int t = blockIdx.x;
    int d = blockIdx.y * 128 + threadIdx.x;
    __shared__ float al[SRC];
    al[threadIdx.x] = g_alpha[t * SRC + threadIdx.x];
    __syncthreads();
    float c = 0.f;
#pragma unroll 16
    for (int s = 0; s < SRC; s++) c = fmaf(al[s], g_fencs[s * D + d], c);
    g_CH[t * 2 * D + d] = c;
    g_CH[t * 2 * D + D + d] = g_H[t * D + d];
}

// ---------------- K4: M = tanh(CH @ Wm^T + bm), emitted as bf16 ----------------
__global__ void m_kernel(const float* __restrict__ Wm, const float* __restrict__ bm) {
    int w = threadIdx.x >> 5, l = threadIdx.x & 31;
    int t0 = blockIdx.y * 8;
#pragma unroll 1
    for (int dd = 0; dd < 8; dd++) {
        int d = blockIdx.x * 64 + w * 8 + dd;
        float4 wv[8];
#pragma unroll
        for (int j = 0; j < 8; j++) wv[j] = *(const float4*)&Wm[d * 2 * D + l * 4 + j * 128];
#pragma unroll
        for (int tt = 0; tt < 8; tt++) {
            int t = t0 + tt;
            float acc = 0.f;
#pragma unroll
            for (int j = 0; j < 8; j++) {
                float4 cv = *(const float4*)&g_CH[t * 2 * D + l * 4 + j * 128];
                acc += wv[j].x * cv.x + wv[j].y * cv.y + wv[j].z * cv.z + wv[j].w * cv.w;
            }
#pragma unroll
            for (int o = 16; o; o >>= 1) acc += __shfl_xor_sync(0xffffffffu, acc, o);
            if (l == 0) g_Mbf[t * D + d] = __float2bfloat16(tanhf(acc + bm[d]));
        }
    }
}

// ---------------- K5: logits via mma.sync bf16 + fused exp-sum + target gather ----
// grid 391 CTAs x 256 threads. M=128 steps, N=128 vocab/CTA, K=512.
// A preloaded to 8 swizzled chunks (128KB); B streamed in K=64 chunks via reg prefetch.
#define OFF_BO 0
#define OFF_TGT 512
#define OFF_SEXP 1024
#define OFF_B 2048
#define OFF_A (2048 + 16384)
#define LOGITS_SMEM (OFF_A + 8 * 16384)

__global__ void __launch_bounds__(256, 1) logits_kernel(const float* __restrict__ Wo,
                                                        const float* __restrict__ bo,
                                                        const int* __restrict__ enums) {
    extern __shared__ char smem[];
    const uint32_t sb = smem_u32(smem);
    const int tid = threadIdx.x;
    const int lane = tid & 31;
    const int wm = (tid >> 5) & 3;   // 4 warps along M (steps)
    const int wn = tid >> 7;         // 2 warps along N (vocab)
    const int vb = blockIdx.x * 128;

    float* bo_s = (float*)(smem + OFF_BO);
    int* tgt_s = (int*)(smem + OFF_TGT);
    float* sexp_s = (float*)(smem + OFF_SEXP);

    for (int i = tid; i < 128; i += 256) {
        int v = vb + i;
        bo_s[i] = (v < VOCAB) ? bo[v] : 0.f;
        tgt_s[i] = enums[i + 1];
        sexp_s[i] = 0.f;
    }

    // A: g_Mbf -> 8 swizzled SMEM chunks (each 128 rows x 64 bf16 = 16KB)
    for (int i = tid * 8; i < TGT_STEPS * D; i += 256 * 8) {
        int t = i >> 9, k = i & 511;
        uint4 v = *(const uint4*)&g_Mbf[i];
        int c = k >> 6, kk = k & 63;
        uint32_t sw = sw128(t * 128 + kk * 2);
        *(uint4*)(smem + OFF_A + c * 16384 + sw) = v;
    }

    // B prefetch setup: thread handles row rowl, half q (32 k each)
    const int rowl = tid >> 1, q = tid & 1;
    const bool vok = (vb + rowl) < VOCAB;
    const float4* wsrc = (const float4*)&Wo[(size_t)(vb + rowl) * D];
    const int qbase = q * 8;

    float4 pf[8];
#pragma unroll
    for (int j = 0; j < 8; j++)
        pf[j] = vok ? wsrc[qbase + j] : make_float4(0.f, 0.f, 0.f, 0.f);

    float cacc[2][8][4];
#pragma unroll
    for (int mi = 0; mi < 2; mi++)
#pragma unroll
        for (int nn = 0; nn < 8; nn++)
#pragma unroll
            for (int e = 0; e < 4; e++) cacc[mi][nn][e] = 0.f;

    const uint32_t bBase = sb + OFF_B;
    const int rowA = wm * 32 + (lane & 15);
    const int kselA = (lane >> 4) << 4;
    const int rowB = wn * 64 + (lane & 7) + ((lane & 16) >> 1);
    const int kselB = (lane & 8) << 1;

#pragma unroll 1
    for (int c = 0; c < 8; c++) {
        // store prefetched chunk (convert fp32 -> bf16, swizzled)
#pragma unroll
        for (int j = 0; j < 8; j++) {
            __nv_bfloat162 lo = __float22bfloat162_rn(make_float2(pf[j].x, pf[j].y));
            __nv_bfloat162 hi = __float22bfloat162_rn(make_float2(pf[j].z, pf[j].w));
            uint2 u;
            u.x = *(uint32_t*)&lo;
            u.y = *(uint32_t*)&hi;
            uint32_t sw = sw128(rowl * 128 + (q * 32 + j * 4) * 2);
            *(uint2*)(smem + OFF_B + sw) = u;
        }
        __syncthreads();
        if (c < 7) {
#pragma unroll
            for (int j = 0; j < 8; j++)
                pf[j] = vok ? wsrc[(c + 1) * 16 + qbase + j] : make_float4(0.f, 0.f, 0.f, 0.f);
        }
        const uint32_t aBase = sb + OFF_A + c * 16384;
#pragma unroll
        for (int kk = 0; kk < 4; kk++) {
            uint32_t a[2][4];
#pragma unroll
            for (int mi = 0; mi < 2; mi++) {
                uint32_t off = (rowA + mi * 16) * 128 + kk * 32 + kselA;
                ldsm4(a[mi][0], a[mi][1], a[mi][2], a[mi][3], aBase + sw128(off));
            }
            uint32_t bf[4][4];
#pragma unroll
            for (int n2 = 0; n2 < 4; n2++) {
                uint32_t off = (rowB + n2 * 16) * 128 + kk * 32 + kselB;
                ldsm4(bf[n2][0], bf[n2][1], bf[n2][2], bf[n2][3], bBase + sw128(off));
            }
#pragma unroll
            for (int mi = 0; mi < 2; mi++)
#pragma unroll
                for (int nn = 0; nn < 8; nn++) {
                    uint32_t b0 = bf[nn >> 1][(nn & 1) * 2];
                    uint32_t b1 = bf[nn >> 1][(nn & 1) * 2 + 1];
                    mma_bf16(cacc[mi][nn], a[mi][0], a[mi][1], a[mi][2], a[mi][3], b0, b1);
                }
        }
        __syncthreads();
    }

    // epilogue: fragment rows are step indices
#pragma unroll
    for (int mi = 0; mi < 2; mi++) {
        int r0 = wm * 32 + mi * 16 + (lane >> 2);
        int r1 = r0 + 8;
        float s0 = 0.f, s1 = 0.f;
#pragma unroll
        for (int nn = 0; nn < 8; nn++) {
            int col = wn * 64 + nn * 8 + 2 * (lane & 3);
            const float* cc = cacc[mi][nn];
#pragma unroll
            for (int e = 0; e < 2; e++) {
                int v = vb + col + e;
                if (v < VOCAB) {
                    float lg0 = cc[e] + bo_s[col + e];
                    float lg1 = cc[2 + e] + bo_s[col + e];
                    s0 += __expf(lg0);
                    s1 += __expf(lg1);
                    if (v == tgt_s[r0]) g_picked[r0] = lg0;
                    if (v == tgt_s[r1]) g_picked[r1] = lg1;
                }
            }
        }
        s0 += __shfl_xor_sync(0xffffffffu, s0, 1);
        s0 += __shfl_xor_sync(0xffffffffu, s0, 2);
        s1 += __shfl_xor_sync(0xffffffffu, s1, 1);
        s1 += __shfl_xor_sync(0xffffffffu, s1, 2);
        if ((lane & 3) == 0) {
            atomicAdd(&sexp_s[r0], s0);
            atomicAdd(&sexp_s[r1], s1);
        }
    }
    __syncthreads();
    for (int i = tid; i < 128; i += 256) atomicAdd(&g_sumexp[i], sexp_s[i]);
}

// ---------------- K6: final reduction ----------------
__global__ void finalize_kernel(float* __restrict__ out) {
    int tid = threadIdx.x;
    float v = g_picked[tid] - logf(g_sumexp[tid]);
    __shared__ float red[4];
    int w = tid >> 5, l = tid & 31;
#pragma unroll
    for (int o = 16; o; o >>= 1) v += __shfl_xor_sync(0xffffffffu, v, o);
    if (l == 0) red[w] = v;
    __syncthreads();
    if (tid == 0) out[0] = red[0] + red[1] + red[2] + red[3];
}

// ---------------- launch ----------------
extern "C" void kernel_launch(void* const* d_in, const int* in_sizes, int n_in,
                              void* d_out, int out_size) {
    const int* fnums = (const int*)d_in[0];
    const int* enums = (const int*)d_in[1];
    const float* emb_f = (const float*)d_in[2];
    const float* Wih_e = (const float*)d_in[3];
    const float* Whh_e = (const float*)d_in[4];
    const float* b_e = (const float*)d_in[5];
    const float* h0_e = (const float*)d_in[6];
    const float* emb_d = (const float*)d_in[7];
    const float* Wih_d = (const float*)d_in[8];
    const float* Whh_d = (const float*)d_in[9];
    const float* b_d = (const float*)d_in[10];
    const float* h0_d = (const float*)d_in[11];
    const float* Wm = (const float*)d_in[12];
    const float* bm = (const float*)d_in[13];
    const float* Wo = (const float*)d_in[14];
    const float* bo = (const float*)d_in[15];
    float* out = (float*)d_out;

    static int smem_set = 0;
    if (!smem_set) {
        cudaFuncSetAttribute(logits_kernel, cudaFuncAttributeMaxDynamicSharedMemorySize,
                             LOGITS_SMEM);
        smem_set = 1;
    }

    init_kernel<<<1, 128>>>();
    pre_kernel<<<dim3(16, 2), 256>>>(fnums, enums, emb_f, emb_d, Wih_e, Wih_d, b_e, b_d);
    recur_kernel<<<dim3(8, 2), 512>>>(Whh_e, Whh_d, h0_e, h0_d);
    attn_scores_kernel<<<128, 256>>>();
    attn_ctx_kernel<<<dim3(128, 4), 128>>>();
    m_kernel<<<dim3(8, 16), 256>>>(Wm, bm);
    logits_kernel<<<(VOCAB + 127) / 128, 256, LOGITS_SMEM>>>(Wo, bo, enums);
    finalize_kernel<<<1, 128>>>(out);
}

// round 5
// speedup vs baseline: 3.0398x; 1.1536x over previous
#include <cuda_runtime.h>
#include <cuda_bf16.h>
#include <cstdint>

#define D 512
#define SRC 128
#define TGT_STEPS 128
#define VOCAB 50000

typedef unsigned long long u64;

// ---------------- scratch (device globals; no allocation allowed) ----------------
__device__ __align__(16) float g_xpre[SRC * D];
__device__ __align__(16) float g_epre[TGT_STEPS * D];
__device__ __align__(16) float g_fencs[SRC * D];
__device__ __align__(16) float g_H[TGT_STEPS * D];
__device__ __align__(16) float g_alpha[TGT_STEPS * SRC];
__device__ __align__(16) float g_CH[TGT_STEPS * 2 * D];
__device__ __align__(16) __nv_bfloat16 g_Mbf[TGT_STEPS * D];
__device__ float g_sumexp[TGT_STEPS];
__device__ float g_picked[TGT_STEPS];

// ---------------- helpers ----------------
__device__ __forceinline__ u64 pk2(float x, float y) {
    u64 r;
    asm("mov.b64 %0, {%1, %2};" : "=l"(r) : "f"(x), "f"(y));
    return r;
}
__device__ __forceinline__ float2 upk2(u64 v) {
    float2 r;
    asm("mov.b64 {%0, %1}, %2;" : "=f"(r.x), "=f"(r.y) : "l"(v));
    return r;
}
__device__ __forceinline__ void fma2(u64& d, u64 a, u64 b) {
    asm volatile("fma.rn.f32x2 %0, %1, %2, %0;" : "+l"(d) : "l"(a), "l"(b));
}
__device__ __forceinline__ void st_cluster_f32(uint32_t saddr, uint32_t rank, float v) {
    uint32_t r;
    asm volatile("mapa.shared::cluster.u32 %0, %1, %2;" : "=r"(r) : "r"(saddr), "r"(rank));
    asm volatile("st.shared::cluster.f32 [%0], %1;" :: "r"(r), "f"(v) : "memory");
}
__device__ __forceinline__ uint32_t smem_u32(const void* p) {
    uint32_t a;
    asm("{ .reg .u64 t; cvta.to.shared.u64 t, %1; cvt.u32.u64 %0, t; }" : "=r"(a) : "l"(p));
    return a;
}
__device__ __forceinline__ void ldsm4(uint32_t& r0, uint32_t& r1, uint32_t& r2, uint32_t& r3,
                                      uint32_t addr) {
    asm volatile("ldmatrix.sync.aligned.m8n8.x4.shared.b16 {%0,%1,%2,%3}, [%4];"
                 : "=r"(r0), "=r"(r1), "=r"(r2), "=r"(r3) : "r"(addr));
}
__device__ __forceinline__ void mma_bf16(float* c, uint32_t a0, uint32_t a1, uint32_t a2,
                                         uint32_t a3, uint32_t b0, uint32_t b1) {
    asm volatile(
        "mma.sync.aligned.m16n8k16.row.col.f32.bf16.bf16.f32 "
        "{%0,%1,%2,%3}, {%4,%5,%6,%7}, {%8,%9}, {%0,%1,%2,%3};"
        : "+f"(c[0]), "+f"(c[1]), "+f"(c[2]), "+f"(c[3])
        : "r"(a0), "r"(a1), "r"(a2), "r"(a3), "r"(b0), "r"(b1));
}
__device__ __forceinline__ uint32_t sw128(uint32_t off) { return off ^ ((off >> 3) & 0x70); }
__device__ __forceinline__ float fast_tanh(float x) {
    float e = __expf(2.f * x);
    return __fdividef(e - 1.f, e + 1.f);
}

// ---------------- init ----------------
__global__ void init_kernel() {
    int i = threadIdx.x;
    if (i < TGT_STEPS) g_sumexp[i] = 0.f;
}

// ---------------- K1/K4: tiled SGEMM  out[m, 0..511] = act(Xrow(m) . W[n,:] + bias[n]) ----
// 32x64 output tile, 256 threads (16x16), 2x4 micro-tile, f32x2 packed FMA.
// X row m: idx ? X + idx[m]*K : X + m*K.   W: [512][K] row-major.
__global__ void __launch_bounds__(256) gemm_kernel(
    const float* __restrict__ X0, const int* __restrict__ idx0,
    const float* __restrict__ W0, const float* __restrict__ b0,
    const float* __restrict__ X1, const int* __restrict__ idx1,
    const float* __restrict__ W1, const float* __restrict__ b1,
    float* __restrict__ oF0, float* __restrict__ oF1,
    __nv_bfloat16* __restrict__ oB,
    int K, int applyTanh) {
    const int z = blockIdx.z;
    const float* X = z ? X1 : X0;
    const int* idx = z ? idx1 : idx0;
    const float* W = z ? W1 : W0;
    const float* bias = z ? b1 : b0;
    float* outF = z ? oF1 : oF0;

    __shared__ __align__(16) float Xs[64][34];
    __shared__ __align__(16) float Ws[64][68];
    __shared__ int roff[32];

    const int tid = threadIdx.x;
    const int tx = tid & 15, ty = tid >> 4;
    const int mbase = blockIdx.y * 32;
    const int nbase = blockIdx.x * 64;

    if (tid < 32) {
        int m = mbase + tid;
        roff[tid] = (idx ? idx[m] : m) * K;
    }
    __syncthreads();

    u64 acc[2][2] = {{0ull, 0ull}, {0ull, 0ull}};

    for (int kt = 0; kt < K; kt += 64) {
#pragma unroll
        for (int j = 0; j < 2; j++) {
            int id = tid * 2 + j;
            int m = id >> 4, kq = id & 15;
            float4 v = *(const float4*)&X[roff[m] + kt + kq * 4];
            Xs[kq * 4 + 0][m] = v.x;
            Xs[kq * 4 + 1][m] = v.y;
            Xs[kq * 4 + 2][m] = v.z;
            Xs[kq * 4 + 3][m] = v.w;
        }
#pragma unroll
        for (int j = 0; j < 4; j++) {
            int id = tid + 256 * j;
            int n = id >> 4, kq = id & 15;
            float4 v = *(const float4*)&W[(size_t)(nbase + n) * K + kt + kq * 4];
            Ws[kq * 4 + 0][n] = v.x;
            Ws[kq * 4 + 1][n] = v.y;
            Ws[kq * 4 + 2][n] = v.z;
            Ws[kq * 4 + 3][n] = v.w;
        }
        __syncthreads();
#pragma unroll
        for (int k = 0; k < 64; k++) {
            float2 a = *(const float2*)&Xs[k][ty * 2];
            float4 b = *(const float4*)&Ws[k][tx * 4];
            u64 bp0 = pk2(b.x, b.y), bp1 = pk2(b.z, b.w);
            u64 a0 = pk2(a.x, a.x), a1 = pk2(a.y, a.y);
            fma2(acc[0][0], a0, bp0);
            fma2(acc[0][1], a0, bp1);
            fma2(acc[1][0], a1, bp0);
            fma2(acc[1][1], a1, bp1);
        }
        __syncthreads();
    }
#pragma unroll
    for (int r = 0; r < 2; r++) {
        int m = mbase + ty * 2 + r;
        float2 v0 = upk2(acc[r][0]), v1 = upk2(acc[r][1]);
        float o[4] = {v0.x, v0.y, v1.x, v1.y};
#pragma unroll
        for (int i = 0; i < 4; i++) {
            int n = nbase + tx * 4 + i;
            float val = o[i] + bias[n];
            if (applyTanh) val = fast_tanh(val);
            if (outF) outF[m * D + n] = val;
            else oB[m * D + n] = __float2bfloat16(val);
        }
    }
}

// ---------------- K2: both recurrences, one 8-CTA cluster each ----------------
__global__ void __cluster_dims__(8, 1, 1) __launch_bounds__(512, 1)
recur_kernel(const float* __restrict__ Whh_e, const float* __restrict__ Whh_d,
             const float* __restrict__ h0_e, const float* __restrict__ h0_d) {
    const int ph = blockIdx.y;
    const float* W = ph ? Whh_d : Whh_e;
    const float* h0 = ph ? h0_d : h0_e;
    const float* pre = ph ? g_epre : g_xpre;
    float* outg = ph ? g_H : g_fencs;

    __shared__ __align__(16) float hbuf[2][D];
    __shared__ float pre_s[128 * 64];

    const int tid = threadIdx.x;
    const int rl = tid >> 3;
    const int sub = tid & 7;
    const uint32_t rank = blockIdx.x;
    const int row = rank * 64 + rl;

    // weights packed as f32x2: 32 u64 per thread
    u64 wv2[32];
#pragma unroll
    for (int j = 0; j < 16; j++) {
        ulonglong2 t = *(const ulonglong2*)&W[row * D + j * 32 + sub * 4];
        wv2[2 * j] = t.x;
        wv2[2 * j + 1] = t.y;
    }

    for (int i = tid; i < 128 * 64; i += 512) {
        int t = i >> 6, r = i & 63;
        pre_s[i] = pre[t * D + rank * 64 + r];
    }
    if (tid < D) hbuf[0][tid] = h0[tid];
    __syncthreads();

    int p = 0;
    for (int t = 0; t < 128; t++) {
        const float* hp = hbuf[p];
        u64 A0 = 0ull, A1 = 0ull;
#pragma unroll
        for (int j = 0; j < 16; j++) {
            ulonglong2 hv = *(const ulonglong2*)&hp[j * 32 + sub * 4];
            fma2(A0, wv2[2 * j], hv.x);
            fma2(A1, wv2[2 * j + 1], hv.y);
        }
        float2 f0 = upk2(A0), f1 = upk2(A1);
        float acc = (f0.x + f0.y) + (f1.x + f1.y);
#pragma unroll
        for (int o = 4; o; o >>= 1) acc += __shfl_xor_sync(0xffffffffu, acc, o);
        if (sub == 0) {
            float h = fast_tanh(acc + pre_s[t * 64 + rl]);
            uint32_t dst = (uint32_t)__cvta_generic_to_shared(&hbuf[p ^ 1][row]);
#pragma unroll
            for (uint32_t c = 0; c < 8; c++) st_cluster_f32(dst, c, h);
            outg[t * D + row] = h;
        }
        asm volatile("barrier.cluster.arrive.aligned;" ::: "memory");
        asm volatile("barrier.cluster.wait.aligned;" ::: "memory");
        p ^= 1;
    }
}

// ---------------- K3a: scores + softmax -> g_alpha ----------------
__global__ void attn_scores_kernel() {
    int t = blockIdx.x;
    int tid = threadIdx.x, w = tid >> 5, l = tid & 31;
    __shared__ __align__(16) float hs[D];
    __shared__ float sc[SRC];
    __shared__ float red[16];
    for (int i = tid; i < D; i += 256) hs[i] = g_H[t * D + i];
    __syncthreads();
#pragma unroll 1
    for (int si = 0; si < 16; si++) {
        int s2 = w * 16 + si;
        float acc = 0.f;
#pragma unroll
        for (int j = 0; j < 4; j++) {
            float4 fv = *(const float4*)&g_fencs[s2 * D + l * 4 + j * 128];
            float4 hv = *(const float4*)&hs[l * 4 + j * 128];
            acc += fv.x * hv.x + fv.y * hv.y + fv.z * hv.z + fv.w * hv.w;
        }
#pragma unroll
        for (int o = 16; o; o >>= 1) acc += __shfl_xor_sync(0xffffffffu, acc, o);
        if (l == 0) sc[s2] = acc;
    }
    __syncthreads();
    float v = (tid < SRC) ? sc[tid] : -1e30f;
    float mx = v;
#pragma unroll
    for (int o = 16; o; o >>= 1) mx = fmaxf(mx, __shfl_xor_sync(0xffffffffu, mx, o));
    if (l == 0) red[w] = mx;
    __syncthreads();
    mx = fmaxf(fmaxf(red[0], red[1]), fmaxf(red[2], red[3]));
    float e = (tid < SRC) ? __expf(v - mx) : 0.f;
    float sm = e;
#pragma unroll
    for (int o = 16; o; o >>= 1) sm += __shfl_xor_sync(0xffffffffu, sm, o);
    if (l == 0) red[8 + w] = sm;
    __syncthreads();
    sm = red[8] + red[9] + red[10] + red[11];
    if (tid < SRC) g_alpha[t * SRC + tid] = e / sm;
}

// ---------------- K3b: context + assemble CH ----------------
__global__ void attn_ctx_kernel() {
    int t = blockIdx.x;
    int d = blockIdx.y * 128 + threadIdx.x;
    __shared__ float al[SRC];
    al[threadIdx.x] = g_alpha[t * SRC + threadIdx.x];
    __syncthreads();
    float c = 0.f;
#pragma unroll 16
    for (int s = 0; s < SRC; s++) c = fmaf(al[s], g_fencs[s * D + d], c);
    g_CH[t * 2 * D + d] = c;
    g_CH[t * 2 * D + D + d] = g_H[t * D + d];
}

// ---------------- K5: logits via mma.sync bf16 + fused exp-sum + target gather ----
// grid 391 CTAs x 256 threads. M=128 steps, N=128 vocab/CTA, K=512.
// A preloaded to 8 swizzled chunks; B double-buffered, streamed via reg prefetch.
#define OFF_BO 0
#define OFF_TGT 512
#define OFF_SEXP 1024
#define OFF_B 2048
#define OFF_A (2048 + 2 * 16384)
#define LOGITS_SMEM (OFF_A + 8 * 16384)

__global__ void __launch_bounds__(256, 1) logits_kernel(const float* __restrict__ Wo,
                                                        const float* __restrict__ bo,
                                                        const int* __restrict__ enums) {
    extern __shared__ char smem[];
    const uint32_t sb = smem_u32(smem);
    const int tid = threadIdx.x;
    const int lane = tid & 31;
    const int wm = (tid >> 5) & 3;
    const int wn = tid >> 7;
    const int vb = blockIdx.x * 128;

    float* bo_s = (float*)(smem + OFF_BO);
    int* tgt_s = (int*)(smem + OFF_TGT);
    float* sexp_s = (float*)(smem + OFF_SEXP);

    for (int i = tid; i < 128; i += 256) {
        int v = vb + i;
        bo_s[i] = (v < VOCAB) ? bo[v] : 0.f;
        tgt_s[i] = enums[i + 1];
        sexp_s[i] = 0.f;
    }

    for (int i = tid * 8; i < TGT_STEPS * D; i += 256 * 8) {
        int t = i >> 9, k = i & 511;
        uint4 v = *(const uint4*)&g_Mbf[i];
        int c = k >> 6, kk = k & 63;
        uint32_t sw = sw128(t * 128 + kk * 2);
        *(uint4*)(smem + OFF_A + c * 16384 + sw) = v;
    }

    const int rowl = tid >> 1, q = tid & 1;
    const bool vok = (vb + rowl) < VOCAB;
    const float4* wsrc = (const float4*)&Wo[(size_t)(vb + rowl) * D];
    const int qbase = q * 8;

    float4 pf[8];
#pragma unroll
    for (int j = 0; j < 8; j++)
        pf[j] = vok ? wsrc[qbase + j] : make_float4(0.f, 0.f, 0.f, 0.f);

    float cacc[2][8][4];
#pragma unroll
    for (int mi = 0; mi < 2; mi++)
#pragma unroll
        for (int nn = 0; nn < 8; nn++)
#pragma unroll
            for (int e = 0; e < 4; e++) cacc[mi][nn][e] = 0.f;

    const int rowA = wm * 32 + (lane & 15);
    const int kselA = (lane >> 4) << 4;
    const int rowB = wn * 64 + (lane & 7) + ((lane & 16) >> 1);
    const int kselB = (lane & 8) << 1;

#pragma unroll 1
    for (int c = 0; c < 8; c++) {
        char* bbuf = smem + OFF_B + (c & 1) * 16384;
#pragma unroll
        for (int j = 0; j < 8; j++) {
            __nv_bfloat162 lo = __float22bfloat162_rn(make_float2(pf[j].x, pf[j].y));
            __nv_bfloat162 hi = __float22bfloat162_rn(make_float2(pf[j].z, pf[j].w));
            uint2 u;
            u.x = *(uint32_t*)&lo;
            u.y = *(uint32_t*)&hi;
            uint32_t sw = sw128(rowl * 128 + (q * 32 + j * 4) * 2);
            *(uint2*)(bbuf + sw) = u;
        }
        __syncthreads();
        if (c < 7) {
#pragma unroll
            for (int j = 0; j < 8; j++)
                pf[j] = vok ? wsrc[(c + 1) * 16 + qbase + j] : make_float4(0.f, 0.f, 0.f, 0.f);
        }
        const uint32_t aBase = sb + OFF_A + c * 16384;
        const uint32_t bBase = sb + OFF_B + (c & 1) * 16384;
#pragma unroll
        for (int kk = 0; kk < 4; kk++) {
            uint32_t a[2][4];
#pragma unroll
            for (int mi = 0; mi < 2; mi++) {
                uint32_t off = (rowA + mi * 16) * 128 + kk * 32 + kselA;
                ldsm4(a[mi][0], a[mi][1], a[mi][2], a[mi][3], aBase + sw128(off));
            }
            uint32_t bf[4][4];
#pragma unroll
            for (int n2 = 0; n2 < 4; n2++) {
                uint32_t off = (rowB + n2 * 16) * 128 + kk * 32 + kselB;
                ldsm4(bf[n2][0], bf[n2][1], bf[n2][2], bf[n2][3], bBase + sw128(off));
            }
#pragma unroll
            for (int mi = 0; mi < 2; mi++)
#pragma unroll
                for (int nn = 0; nn < 8; nn++) {
                    uint32_t b0 = bf[nn >> 1][(nn & 1) * 2];
                    uint32_t b1 = bf[nn >> 1][(nn & 1) * 2 + 1];
                    mma_bf16(cacc[mi][nn], a[mi][0], a[mi][1], a[mi][2], a[mi][3], b0, b1);
                }
        }
    }

#pragma unroll
    for (int mi = 0; mi < 2; mi++) {
        int r0 = wm * 32 + mi * 16 + (lane >> 2);
        int r1 = r0 + 8;
        float s0 = 0.f, s1 = 0.f;
#pragma unroll
        for (int nn = 0; nn < 8; nn++) {
            int col = wn * 64 + nn * 8 + 2 * (lane & 3);
            const float* cc = cacc[mi][nn];
#pragma unroll
            for (int e = 0; e < 2; e++) {
                int v = vb + col + e;
                if (v < VOCAB) {
                    float lg0 = cc[e] + bo_s[col + e];
                    float lg1 = cc[2 + e] + bo_s[col + e];
                    s0 += __expf(lg0);
                    s1 += __expf(lg1);
                    if (v == tgt_s[r0]) g_picked[r0] = lg0;
                    if (v == tgt_s[r1]) g_picked[r1] = lg1;
                }
            }
        }
        s0 += __shfl_xor_sync(0xffffffffu, s0, 1);
        s0 += __shfl_xor_sync(0xffffffffu, s0, 2);
        s1 += __shfl_xor_sync(0xffffffffu, s1, 1);
        s1 += __shfl_xor_sync(0xffffffffu, s1, 2);
        if ((lane & 3) == 0) {
            atomicAdd(&sexp_s[r0], s0);
            atomicAdd(&sexp_s[r1], s1);
        }
    }
    __syncthreads();
    for (int i = tid; i < 128; i += 256) atomicAdd(&g_sumexp[i], sexp_s[i]);
}

// ---------------- K6: final reduction ----------------
__global__ void finalize_kernel(float* __restrict__ out) {
    int tid = threadIdx.x;
    float v = g_picked[tid] - logf(g_sumexp[tid]);
    __shared__ float red[4];
    int w = tid >> 5, l = tid & 31;
#pragma unroll
    for (int o = 16; o; o >>= 1) v += __shfl_xor_sync(0xffffffffu, v, o);
    if (l == 0) red[w] = v;
    __syncthreads();
    if (tid == 0) out[0] = red[0] + red[1] + red[2] + red[3];
}

// ---------------- launch ----------------
extern "C" void kernel_launch(void* const* d_in, const int* in_sizes, int n_in,
                              void* d_out, int out_size) {
    const int* fnums = (const int*)d_in[0];
    const int* enums = (const int*)d_in[1];
    const float* emb_f = (const float*)d_in[2];
    const float* Wih_e = (const float*)d_in[3];
    const float* Whh_e = (const float*)d_in[4];
    const float* b_e = (const float*)d_in[5];
    const float* h0_e = (const float*)d_in[6];
    const float* emb_d = (const float*)d_in[7];
    const float* Wih_d = (const float*)d_in[8];
    const float* Whh_d = (const float*)d_in[9];
    const float* b_d = (const float*)d_in[10];
    const float* h0_d = (const float*)d_in[11];
    const float* Wm = (const float*)d_in[12];
    const float* bm = (const float*)d_in[13];
    const float* Wo = (const float*)d_in[14];
    const float* bo = (const float*)d_in[15];
    float* out = (float*)d_out;

    static int inited = 0;
    static float *p_xpre, *p_epre, *p_CH;
    static __nv_bfloat16* p_Mbf;
    if (!inited) {
        cudaFuncSetAttribute(logits_kernel, cudaFuncAttributeMaxDynamicSharedMemorySize,
                             LOGITS_SMEM);
        cudaGetSymbolAddress((void**)&p_xpre, g_xpre);
        cudaGetSymbolAddress((void**)&p_epre, g_epre);
        cudaGetSymbolAddress((void**)&p_CH, g_CH);
        cudaGetSymbolAddress((void**)&p_Mbf, g_Mbf);
        inited = 1;
    }

    init_kernel<<<1, 128>>>();
    // pre-activations: encoder (z=0) + decoder (z=1) concurrently
    gemm_kernel<<<dim3(8, 4, 2), 256>>>(emb_f, fnums, Wih_e, b_e,
                                        emb_d, enums, Wih_d, b_d,
                                        p_xpre, p_epre, nullptr, D, 0);
    recur_kernel<<<dim3(8, 2), 512>>>(Whh_e, Whh_d, h0_e, h0_d);
    attn_scores_kernel<<<128, 256>>>();
    attn_ctx_kernel<<<dim3(128, 4), 128>>>();
    // M = tanh(CH @ Wm^T + bm) -> bf16
    gemm_kernel<<<dim3(8, 4, 1), 256>>>(p_CH, nullptr, Wm, bm,
                                        p_CH, nullptr, Wm, bm,
                                        nullptr, nullptr, p_Mbf, 2 * D, 1);
    logits_kernel<<<(VOCAB + 127) / 128, 256, LOGITS_SMEM>>>(Wo, bo, enums);
    finalize_kernel<<<1, 128>>>(out);
}

// round 7
// speedup vs baseline: 3.4295x; 1.1282x over previous
#include <cuda_runtime.h>
#include <cuda_bf16.h>
#include <cstdint>

#define D 512
#define SRC 128
#define TGT_STEPS 128
#define VOCAB 50000

typedef unsigned long long u64;

// ---------------- scratch (device globals; no allocation allowed) ----------------
__device__ __align__(16) float g_xpre[SRC * D];
__device__ __align__(16) float g_epre[TGT_STEPS * D];
__device__ __align__(16) float g_fencs[SRC * D];
__device__ __align__(16) float g_H[TGT_STEPS * D];
__device__ __align__(16) float g_alpha[TGT_STEPS * SRC];
__device__ __align__(16) float g_CH[TGT_STEPS * 2 * D];
__device__ __align__(16) __nv_bfloat16 g_Mbf[TGT_STEPS * D];
__device__ __align__(16) __nv_bfloat16 g_Wobf[VOCAB * D];
__device__ float g_sumexp[TGT_STEPS];
__device__ float g_picked[TGT_STEPS];

// ---------------- helpers ----------------
__device__ __forceinline__ u64 pk2(float x, float y) {
    u64 r;
    asm("mov.b64 %0, {%1, %2};" : "=l"(r) : "f"(x), "f"(y));
    return r;
}
__device__ __forceinline__ float2 upk2(u64 v) {
    float2 r;
    asm("mov.b64 {%0, %1}, %2;" : "=f"(r.x), "=f"(r.y) : "l"(v));
    return r;
}
__device__ __forceinline__ void fma2(u64& d, u64 a, u64 b) {
    asm volatile("fma.rn.f32x2 %0, %1, %2, %0;" : "+l"(d) : "l"(a), "l"(b));
}
__device__ __forceinline__ uint32_t smem_u32(const void* p) {
    uint32_t a;
    asm("{ .reg .u64 t; cvta.to.shared.u64 t, %1; cvt.u32.u64 %0, t; }" : "=r"(a) : "l"(p));
    return a;
}
__device__ __forceinline__ uint32_t mapa_u32(uint32_t saddr, uint32_t rank) {
    uint32_t r;
    asm volatile("mapa.shared::cluster.u32 %0, %1, %2;" : "=r"(r) : "r"(saddr), "r"(rank));
    return r;
}
__device__ __forceinline__ void st_cluster_f32(uint32_t raddr, float v) {
    asm volatile("st.shared::cluster.f32 [%0], %1;" :: "r"(raddr), "f"(v) : "memory");
}
__device__ __forceinline__ void ldsm4(uint32_t& r0, uint32_t& r1, uint32_t& r2, uint32_t& r3,
                                      uint32_t addr) {
    asm volatile("ldmatrix.sync.aligned.m8n8.x4.shared.b16 {%0,%1,%2,%3}, [%4];"
                 : "=r"(r0), "=r"(r1), "=r"(r2), "=r"(r3) : "r"(addr));
}
__device__ __forceinline__ void mma_bf16(float* c, uint32_t a0, uint32_t a1, uint32_t a2,
                                         uint32_t a3, uint32_t b0, uint32_t b1) {
    asm volatile(
        "mma.sync.aligned.m16n8k16.row.col.f32.bf16.bf16.f32 "
        "{%0,%1,%2,%3}, {%4,%5,%6,%7}, {%8,%9}, {%0,%1,%2,%3};"
        : "+f"(c[0]), "+f"(c[1]), "+f"(c[2]), "+f"(c[3])
        : "r"(a0), "r"(a1), "r"(a2), "r"(a3), "r"(b0), "r"(b1));
}
__device__ __forceinline__ uint32_t sw128(uint32_t off) { return off ^ ((off >> 3) & 0x70); }
__device__ __forceinline__ float fast_tanh(float x) {
    float e = __expf(2.f * x);
    return __fdividef(e - 1.f, e + 1.f);
}

// ---------------- K1/K4: tiled SGEMM  out[m, n] = act(Xrow(m) . W[n,:] + bias[n]) ----
__global__ void __launch_bounds__(256) gemm_kernel(
    const float* __restrict__ X0, const int* __restrict__ idx0,
    const float* __restrict__ W0, const float* __restrict__ b0,
    const float* __restrict__ X1, const int* __restrict__ idx1,
    const float* __restrict__ W1, const float* __restrict__ b1,
    float* __restrict__ oF0, float* __restrict__ oF1,
    __nv_bfloat16* __restrict__ oB,
    int K, int applyTanh) {
    const int z = blockIdx.z;
    const float* X = z ? X1 : X0;
    const int* idx = z ? idx1 : idx0;
    const float* W = z ? W1 : W0;
    const float* bias = z ? b1 : b0;
    float* outF = z ? oF1 : oF0;

    __shared__ __align__(16) float Xs[64][34];
    __shared__ __align__(16) float Ws[64][68];
    __shared__ int roff[32];

    const int tid = threadIdx.x;
    const int tx = tid & 15, ty = tid >> 4;
    const int mbase = blockIdx.y * 32;
    const int nbase = blockIdx.x * 64;

    // fold init: zero g_sumexp before logits runs (this kernel precedes logits)
    if (oB && blockIdx.x == 0 && blockIdx.y == 0 && z == 0 && tid < TGT_STEPS)
        g_sumexp[tid] = 0.f;

    if (tid < 32) {
        int m = mbase + tid;
        roff[tid] = (idx ? idx[m] : m) * K;
    }
    __syncthreads();

    u64 acc[2][2] = {{0ull, 0ull}, {0ull, 0ull}};

    for (int kt = 0; kt < K; kt += 64) {
#pragma unroll
        for (int j = 0; j < 2; j++) {
            int id = tid * 2 + j;
            int m = id >> 4, kq = id & 15;
            float4 v = *(const float4*)&X[roff[m] + kt + kq * 4];
            Xs[kq * 4 + 0][m] = v.x;
            Xs[kq * 4 + 1][m] = v.y;
            Xs[kq * 4 + 2][m] = v.z;
            Xs[kq * 4 + 3][m] = v.w;
        }
#pragma unroll
        for (int j = 0; j < 4; j++) {
            int id = tid + 256 * j;
            int n = id >> 4, kq = id & 15;
            float4 v = *(const float4*)&W[(size_t)(nbase + n) * K + kt + kq * 4];
            Ws[kq * 4 + 0][n] = v.x;
            Ws[kq * 4 + 1][n] = v.y;
            Ws[kq * 4 + 2][n] = v.z;
            Ws[kq * 4 + 3][n] = v.w;
        }
        __syncthreads();
#pragma unroll
        for (int k = 0; k < 64; k++) {
            float2 a = *(const float2*)&Xs[k][ty * 2];
            float4 b = *(const float4*)&Ws[k][tx * 4];
            u64 bp0 = pk2(b.x, b.y), bp1 = pk2(b.z, b.w);
            u64 a0 = pk2(a.x, a.x), a1 = pk2(a.y, a.y);
            fma2(acc[0][0], a0, bp0);
            fma2(acc[0][1], a0, bp1);
            fma2(acc[1][0], a1, bp0);
            fma2(acc[1][1], a1, bp1);
        }
        __syncthreads();
    }
#pragma unroll
    for (int r = 0; r < 2; r++) {
        int m = mbase + ty * 2 + r;
        float2 v0 = upk2(acc[r][0]), v1 = upk2(acc[r][1]);
        float o[4] = {v0.x, v0.y, v1.x, v1.y};
#pragma unroll
        for (int i = 0; i < 4; i++) {
            int n = nbase + tx * 4 + i;
            float val = o[i] + bias[n];
            if (applyTanh) val = fast_tanh(val);
            if (outF) outF[m * D + n] = val;
            else oB[m * D + n] = __float2bfloat16(val);
        }
    }
}

// ---------------- K2: recurrences (y=0,1: 8-CTA clusters) + Wo->bf16 convert (y>=2) ----
// Recur: thread (rl, sub); all 8 sub-lanes hold the row sum after xor-reduce, and
// lane 'sub' stores h to CTA rank 'sub' (parallel DSMEM broadcast), then barrier.cluster.
// Converter CTAs (y>=2) stream Wo fp32 -> g_Wobf bf16, overlapped with the latency-bound recur.
#define CONV_YS 6
__global__ void __cluster_dims__(8, 1, 1) __launch_bounds__(512, 1)
recur_kernel(const float* __restrict__ Whh_e, const float* __restrict__ Whh_d,
             const float* __restrict__ h0_e, const float* __restrict__ h0_d,
             const float* __restrict__ Wo) {
    const int tid = threadIdx.x;

    if (blockIdx.y >= 2) {
        // ---- Wo fp32 -> bf16 converter ----
        const size_t n4 = (size_t)VOCAB * D / 4;  // float4 count
        const size_t gt = (size_t)((blockIdx.y - 2) * 8 + blockIdx.x) * 512 + tid;
        const size_t stride = (size_t)CONV_YS * 8 * 512;
        const float4* src = (const float4*)Wo;
        uint2* dst = (uint2*)g_Wobf;
        for (size_t i = gt; i < n4; i += stride) {
            float4 f = src[i];
            __nv_bfloat162 lo = __float22bfloat162_rn(make_float2(f.x, f.y));
            __nv_bfloat162 hi = __float22bfloat162_rn(make_float2(f.z, f.w));
            uint2 u;
            u.x = *(uint32_t*)&lo;
            u.y = *(uint32_t*)&hi;
            dst[i] = u;
        }
        return;
    }

    const int ph = blockIdx.y;
    const float* W = ph ? Whh_d : Whh_e;
    const float* h0 = ph ? h0_d : h0_e;
    const float* pre = ph ? g_epre : g_xpre;
    float* outg = ph ? g_H : g_fencs;

    __shared__ __align__(16) float hbuf[2][D];
    __shared__ float pre_s[128 * 64];

    const int rl = tid >> 3;
    const int sub = tid & 7;
    const uint32_t rank = blockIdx.x;
    const int row = rank * 64 + rl;

    u64 wv2[32];
#pragma unroll
    for (int j = 0; j < 16; j++) {
        ulonglong2 t = *(const ulonglong2*)&W[row * D + j * 32 + sub * 4];
        wv2[2 * j] = t.x;
        wv2[2 * j + 1] = t.y;
    }

    for (int i = tid; i < 128 * 64; i += 512) {
        int t = i >> 6, r = i & 63;
        pre_s[i] = pre[t * D + rank * 64 + r];
    }
    if (tid < D) hbuf[0][tid] = h0[tid];
    __syncthreads();

    // remote address in CTA 'sub' for this thread's row (buffer 0)
    const uint32_t dst_remote0 = mapa_u32(smem_u32(&hbuf[0][row]), (uint32_t)sub);

    int p = 0;
    for (int t = 0; t < 128; t++) {
        const float* hp = hbuf[p];
        u64 A0 = 0ull, A1 = 0ull;
#pragma unroll
        for (int j = 0; j < 16; j++) {
            ulonglong2 hv = *(const ulonglong2*)&hp[j * 32 + sub * 4];
            fma2(A0, wv2[2 * j], hv.x);
            fma2(A1, wv2[2 * j + 1], hv.y);
        }
        float2 f0 = upk2(A0), f1 = upk2(A1);
        float acc = (f0.x + f0.y) + (f1.x + f1.y);
#pragma unroll
        for (int o = 4; o; o >>= 1) acc += __shfl_xor_sync(0xffffffffu, acc, o);
        float h = fast_tanh(acc + pre_s[t * 64 + rl]);
        // parallel broadcast: lane 'sub' stores this row's h into CTA 'sub'
        st_cluster_f32(dst_remote0 + (p ^ 1) * (D * 4), h);
        if (sub == 0) outg[t * D + row] = h;
        asm volatile("barrier.cluster.arrive.aligned;" ::: "memory");
        asm volatile("barrier.cluster.wait.aligned;" ::: "memory");
        p ^= 1;
    }
}

// ---------------- K3a: scores + softmax -> g_alpha ----------------
__global__ void attn_scores_kernel() {
    int t = blockIdx.x;
    int tid = threadIdx.x, w = tid >> 5, l = tid & 31;
    __shared__ __align__(16) float hs[D];
    __shared__ float sc[SRC];
    __shared__ float red[16];
    for (int i = tid; i < D; i += 256) hs[i] = g_H[t * D + i];
    __syncthreads();
#pragma unroll 1
    for (int si = 0; si < 16; si++) {
        int s2 = w * 16 + si;
        float acc = 0.f;
#pragma unroll
        for (int j = 0; j < 4; j++) {
            float4 fv = *(const float4*)&g_fencs[s2 * D + l * 4 + j * 128];
            float4 hv = *(const float4*)&hs[l * 4 + j * 128];
            acc += fv.x * hv.x + fv.y * hv.y + fv.z * hv.z + fv.w * hv.w;
        }
#pragma unroll
        for (int o = 16; o; o >>= 1) acc += __shfl_xor_sync(0xffffffffu, acc, o);
        if (l == 0) sc[s2] = acc;
    }
    __syncthreads();
    float v = (tid < SRC) ? sc[tid] : -1e30f;
    float mx = v;
#pragma unroll
    for (int o = 16; o; o >>= 1) mx = fmaxf(mx, __shfl_xor_sync(0xffffffffu, mx, o));
    if (l == 0) red[w] = mx;
    __syncthreads();
    mx = fmaxf(fmaxf(red[0], red[1]), fmaxf(red[2], red[3]));
    float e = (tid < SRC) ? __expf(v - mx) : 0.f;
    float sm = e;
#pragma unroll
    for (int o = 16; o; o >>= 1) sm += __shfl_xor_sync(0xffffffffu, sm, o);
    if (l == 0) red[8 + w] = sm;
    __syncthreads();
    sm = red[8] + red[9] + red[10] + red[11];
    if (tid < SRC) g_alpha[t * SRC + tid] = e / sm;
}

// ---------------- K3b: context + assemble CH ----------------
__global__ void attn_ctx_kernel() {
    int t = blockIdx.x;
    int d = blockIdx.y * 128 + threadIdx.x;
    __shared__ float al[SRC];
    al[threadIdx.x] = g_alpha[t * SRC + threadIdx.x];
    __syncthreads();
    float c = 0.f;
#pragma unroll 16
    for (int s = 0; s < SRC; s++) c = fmaf(al[s], g_fencs[s * D + d], c);
    g_CH[t * 2 * D + d] = c;
    g_CH[t * 2 * D + D + d] = g_H[t * D + d];
}

// ---------------- K5: logits via mma.sync bf16 (B pre-converted) ----------------
#define OFF_BO 0
#define OFF_TGT 512
#define OFF_SEXP 1024
#define OFF_B 2048
#define OFF_A (2048 + 2 * 16384)
#define LOGITS_SMEM (OFF_A + 8 * 16384)

__global__ void __launch_bounds__(256, 1) logits_kernel(const float* __restrict__ bo,
                                                        const int* __restrict__ enums) {
    extern __shared__ char smem[];
    const uint32_t sb = smem_u32(smem);
    const int tid = threadIdx.x;
    const int lane = tid & 31;
    const int wm = (tid >> 5) & 3;
    const int wn = tid >> 7;
    const int vb = blockIdx.x * 128;

    float* bo_s = (float*)(smem + OFF_BO);
    int* tgt_s = (int*)(smem + OFF_TGT);
    float* sexp_s = (float*)(smem + OFF_SEXP);

    for (int i = tid; i < 128; i += 256) {
        int v = vb + i;
        bo_s[i] = (v < VOCAB) ? bo[v] : 0.f;
        tgt_s[i] = enums[i + 1];
        sexp_s[i] = 0.f;
    }

    for (int i = tid * 8; i < TGT_STEPS * D; i += 256 * 8) {
        int t = i >> 9, k = i & 511;
        uint4 v = *(const uint4*)&g_Mbf[i];
        int c = k >> 6, kk = k & 63;
        uint32_t sw = sw128(t * 128 + kk * 2);
        *(uint4*)(smem + OFF_A + c * 16384 + sw) = v;
    }

    // B: pre-converted bf16; thread (rowl, q) copies 64B (4 uint4) per chunk
    const int rowl = tid >> 1, q = tid & 1;
    const bool vok = (vb + rowl) < VOCAB;
    const uint4* wsrc = (const uint4*)&g_Wobf[(size_t)(vb + rowl) * D];
    const uint4 Z = make_uint4(0u, 0u, 0u, 0u);

    uint4 pf[4];
#pragma unroll
    for (int j = 0; j < 4; j++) pf[j] = vok ? wsrc[q * 4 + j] : Z;

    float cacc[2][8][4];
#pragma unroll
    for (int mi = 0; mi < 2; mi++)
#pragma unroll
        for (int nn = 0; nn < 8; nn++)
#pragma unroll
            for (int e = 0; e < 4; e++) cacc[mi][nn][e] = 0.f;

    const int rowA = wm * 32 + (lane & 15);
    const int kselA = (lane >> 4) << 4;
    const int rowB = wn * 64 + (lane & 7) + ((lane & 16) >> 1);
    const int kselB = (lane & 8) << 1;

#pragma unroll 1
    for (int c = 0; c < 8; c++) {
        char* bbuf = smem + OFF_B + (c & 1) * 16384;
#pragma unroll
        for (int j = 0; j < 4; j++) {
            uint32_t sw = sw128(rowl * 128 + q * 64 + j * 16);
            *(uint4*)(bbuf + sw) = pf[j];
        }
        __syncthreads();
        if (c < 7) {
#pragma unroll
            for (int j = 0; j < 4; j++)
                pf[j] = vok ? wsrc[(c + 1) * 8 + q * 4 + j] : Z;
        }
        const uint32_t aBase = sb + OFF_A + c * 16384;
        const uint32_t bBase = sb + OFF_B + (c & 1) * 16384;
#pragma unroll
        for (int kk = 0; kk < 4; kk++) {
            uint32_t a[2][4];
#pragma unroll
            for (int mi = 0; mi < 2; mi++) {
                uint32_t off = (rowA + mi * 16) * 128 + kk * 32 + kselA;
                ldsm4(a[mi][0], a[mi][1], a[mi][2], a[mi][3], aBase + sw128(off));
            }
            uint32_t bf[4][4];
#pragma unroll
            for (int n2 = 0; n2 < 4; n2++) {
                uint32_t off = (rowB + n2 * 16) * 128 + kk * 32 + kselB;
                ldsm4(bf[n2][0], bf[n2][1], bf[n2][2], bf[n2][3], bBase + sw128(off));
            }
#pragma unroll
            for (int mi = 0; mi < 2; mi++)
#pragma unroll
                for (int nn = 0; nn < 8; nn++) {
                    uint32_t b0 = bf[nn >> 1][(nn & 1) * 2];
                    uint32_t b1 = bf[nn >> 1][(nn & 1) * 2 + 1];
                    mma_bf16(cacc[mi][nn], a[mi][0], a[mi][1], a[mi][2], a[mi][3], b0, b1);
                }
        }
    }

#pragma unroll
    for (int mi = 0; mi < 2; mi++) {
        int r0 = wm * 32 + mi * 16 + (lane >> 2);
        int r1 = r0 + 8;
        float s0 = 0.f, s1 = 0.f;
#pragma unroll
        for (int nn = 0; nn < 8; nn++) {
            int col = wn * 64 + nn * 8 + 2 * (lane & 3);
            const float* cc = cacc[mi][nn];
#pragma unroll
            for (int e = 0; e < 2; e++) {
                int v = vb + col + e;
                if (v < VOCAB) {
                    float lg0 = cc[e] + bo_s[col + e];
                    float lg1 = cc[2 + e] + bo_s[col + e];
                    s0 += __expf(lg0);
                    s1 += __expf(lg1);
                    if (v == tgt_s[r0]) g_picked[r0] = lg0;
                    if (v == tgt_s[r1]) g_picked[r1] = lg1;
                }
            }
        }
        s0 += __shfl_xor_sync(0xffffffffu, s0, 1);
        s0 += __shfl_xor_sync(0xffffffffu, s0, 2);
        s1 += __shfl_xor_sync(0xffffffffu, s1, 1);
        s1 += __shfl_xor_sync(0xffffffffu, s1, 2);
        if ((lane & 3) == 0) {
            atomicAdd(&sexp_s[r0], s0);
            atomicAdd(&sexp_s[r1], s1);
        }
    }
    __syncthreads();
    for (int i = tid; i < 128; i += 256) atomicAdd(&g_sumexp[i], sexp_s[i]);
}

// ---------------- K6: final reduction ----------------
__global__ void finalize_kernel(float* __restrict__ out) {
    int tid = threadIdx.x;
    float v = g_picked[tid] - logf(g_sumexp[tid]);
    __shared__ float red[4];
    int w = tid >> 5, l = tid & 31;
#pragma unroll
    for (int o = 16; o; o >>= 1) v += __shfl_xor_sync(0xffffffffu, v, o);
    if (l == 0) red[w] = v;
    __syncthreads();
    if (tid == 0) out[0] = red[0] + red[1] + red[2] + red[3];
}

// ---------------- launch ----------------
extern "C" void kernel_launch(void* const* d_in, const int* in_sizes, int n_in,
                              void* d_out, int out_size) {
    const int* fnums = (const int*)d_in[0];
    const int* enums = (const int*)d_in[1];
    const float* emb_f = (const float*)d_in[2];
    const float* Wih_e = (const float*)d_in[3];
    const float* Whh_e = (const float*)d_in[4];
    const float* b_e = (const float*)d_in[5];
    const float* h0_e = (const float*)d_in[6];
    const float* emb_d = (const float*)d_in[7];
    const float* Wih_d = (const float*)d_in[8];
    const float* Whh_d = (const float*)d_in[9];
    const float* b_d = (const float*)d_in[10];
    const float* h0_d = (const float*)d_in[11];
    const float* Wm = (const float*)d_in[12];
    const float* bm = (const float*)d_in[13];
    const float* Wo = (const float*)d_in[14];
    const float* bo = (const float*)d_in[15];
    float* out = (float*)d_out;

    static int inited = 0;
    static float *p_xpre, *p_epre, *p_CH;
    static __nv_bfloat16* p_Mbf;
    if (!inited) {
        cudaFuncSetAttribute(logits_kernel, cudaFuncAttributeMaxDynamicSharedMemorySize,
                             LOGITS_SMEM);
        cudaGetSymbolAddress((void**)&p_xpre, g_xpre);
        cudaGetSymbolAddress((void**)&p_epre, g_epre);
        cudaGetSymbolAddress((void**)&p_CH, g_CH);
        cudaGetSymbolAddress((void**)&p_Mbf, g_Mbf);
        inited = 1;
    }

    // pre-activations: encoder (z=0) + decoder (z=1) concurrently
    gemm_kernel<<<dim3(8, 4, 2), 256>>>(emb_f, fnums, Wih_e, b_e,
                                        emb_d, enums, Wih_d, b_d,
                                        p_xpre, p_epre, nullptr, D, 0);
    // recur (y=0,1) + Wo->bf16 conversion (y=2..) overlapped in one launch
    recur_kernel<<<dim3(8, 2 + CONV_YS), 512>>>(Whh_e, Whh_d, h0_e, h0_d, Wo);
    attn_scores_kernel<<<128, 256>>>();
    attn_ctx_kernel<<<dim3(128, 4), 128>>>();
    // M = tanh(CH @ Wm^T + bm) -> bf16 (also zeroes g_sumexp)
    gemm_kernel<<<dim3(8, 4, 1), 256>>>(p_CH, nullptr, Wm, bm,
                                        p_CH, nullptr, Wm, bm,
                                        nullptr, nullptr, p_Mbf, 2 * D, 1);
    logits_kernel<<<(VOCAB + 127) / 128, 256, LOGITS_SMEM>>>(bo, enums);
    finalize_kernel<<<1, 128>>>(out);
}